// round 4
// baseline (speedup 1.0000x reference)
#include <cuda_runtime.h>
#include <cuda_bf16.h>
#include <stdint.h>

// GCN_57501022159512: 2-layer GCN, N=100000 nodes, E=1600000 edges, 64 -> 128 -> 128.
// h1 = relu(gcnconv(x, W1, b1)); t = batchnorm(h1); out = relu(gcnconv(t, W2, b2))
//
// R4 root-cause fix: edge_index is produced by jax.random.randint(dtype=int64)
// which silently yields int32 under default JAX config. Reading it as int64
// ran off the end of the buffer and produced garbage scatter addresses ->
// err 717. Now: runtime dtype detection + decode into int32 scratch.

#define NNODES 100000
#define NEDGES 1600000
#define FIN    64
#define FHID   128
#define BN_EPS 1e-5f

// ---------------- scratch (device globals; no allocs allowed) ----------------
__device__ float g_h1[NNODES * FHID];    // x @ W1
__device__ float g_t [NNODES * FHID];    // agg1 buffer, then relu/bn input in place
__device__ float g_h2[NNODES * FHID];    // bn(t) @ W2
__device__ float g_dinv[NNODES];
__device__ int   g_deg [NNODES];
__device__ float g_stats[2 * FHID];      // sum,sumsq -> then scale,shift
__device__ int   g_eidx[2 * NEDGES];     // decoded int32 edge index [row | col]
__device__ int   g_is64;

// ---------------- kernels ----------------

__global__ void k_zero(float4* __restrict__ out4) {
    const int idx = blockIdx.x * blockDim.x + threadIdx.x;
    const int stride = gridDim.x * blockDim.x;
    const float4 z = make_float4(0.f, 0.f, 0.f, 0.f);
    float4* t4 = reinterpret_cast<float4*>(g_t);
    const int n4 = NNODES * FHID / 4;
    for (int j = idx; j < n4; j += stride) { t4[j] = z; out4[j] = z; }
    for (int j = idx; j < NNODES; j += stride) g_deg[j] = 0;
    if (idx < 2 * FHID) g_stats[idx] = 0.f;
}

// Detect whether the edge_index buffer is int64 or int32.
// If int64 (values < N, little-endian), every odd 32-bit word is 0.
// If int32 (random indices in [0,N)), odd words are ~never all zero.
__global__ void k_detect(const int* __restrict__ w) {
    __shared__ int bad;
    if (threadIdx.x == 0) bad = 0;
    __syncthreads();
    for (int j = threadIdx.x; j < 1024; j += blockDim.x) {
        const int lo = w[2 * j], hi = w[2 * j + 1];
        if (hi != 0 || lo < 0 || lo >= NNODES) bad = 1;
    }
    __syncthreads();
    if (threadIdx.x == 0) g_is64 = (bad == 0) ? 1 : 0;
}

// Decode edge indices into int32 scratch (clamped defensively) + degree count.
__global__ void k_decode(const void* __restrict__ ei) {
    const int idx = blockIdx.x * blockDim.x + threadIdx.x;
    const int stride = gridDim.x * blockDim.x;
    const bool is64 = (g_is64 != 0);
    const long long* e64 = (const long long*)ei;
    const int*       e32 = (const int*)ei;
    for (int e = idx; e < 2 * NEDGES; e += stride) {
        int v = is64 ? (int)e64[e] : e32[e];
        v = min(max(v, 0), NNODES - 1);
        g_eidx[e] = v;
        if (e >= NEDGES) atomicAdd(&g_deg[v], 1);   // col half -> degree
    }
}

__global__ void k_dinv() {
    const int idx = blockIdx.x * blockDim.x + threadIdx.x;
    const int stride = gridDim.x * blockDim.x;
    for (int n = idx; n < NNODES; n += stride)
        g_dinv[n] = rsqrtf((float)(g_deg[n] + 1));
}

// h1 = x @ W1.  128 threads/block; thread f keeps W1[:,f] (64 vals) in regs.
__global__ void k_gemm1(const float* __restrict__ x, const float* __restrict__ W1) {
    __shared__ float sx[4][FIN];
    const int f = threadIdx.x;
    float w[FIN];
#pragma unroll
    for (int k = 0; k < FIN; k++) w[k] = W1[k * FHID + f];

    for (int base = blockIdx.x * 4; base < NNODES; base += gridDim.x * 4) {
        for (int i = threadIdx.x; i < 4 * FIN; i += FHID)
            sx[i >> 6][i & 63] = x[(size_t)base * FIN + i];
        __syncthreads();
#pragma unroll
        for (int j = 0; j < 4; j++) {
            float acc = 0.f;
#pragma unroll
            for (int k = 0; k < FIN; k++) acc = fmaf(sx[j][k], w[k], acc);
            g_h1[(size_t)(base + j) * FHID + f] = acc;
        }
        __syncthreads();
    }
}

// warp-per-edge scatter: agg[col] += h[row] * dinv[row]*dinv[col]
// 128-bit loads; 4 scalar atomicAdd per lane.
__device__ __forceinline__ void scatter_body(const float* __restrict__ h,
                                             float* __restrict__ agg) {
    const int lane = threadIdx.x & 31;
    const int warp = (blockIdx.x * blockDim.x + threadIdx.x) >> 5;
    const int nwarps = (gridDim.x * blockDim.x) >> 5;
    for (int e = warp; e < NEDGES; e += nwarps) {
        const int r = g_eidx[e];
        const int c = g_eidx[NEDGES + e];
        const float norm = g_dinv[r] * g_dinv[c];
        float4 v = *reinterpret_cast<const float4*>(h + (size_t)r * FHID + lane * 4);
        float* dst = agg + (size_t)c * FHID + lane * 4;
        atomicAdd(dst + 0, v.x * norm);
        atomicAdd(dst + 1, v.y * norm);
        atomicAdd(dst + 2, v.z * norm);
        atomicAdd(dst + 3, v.w * norm);
    }
}

__global__ void k_scatter1() { scatter_body(g_h1, g_t); }

__global__ void k_scatter2(float* __restrict__ out) { scatter_body(g_h2, out); }

// t = relu(agg1 + h1*dinv^2 + b1), in place in g_t; accumulate BN partial sums.
__global__ void k_finalize1(const float* __restrict__ b1) {
    const int f = threadIdx.x; // 0..127
    const float bf = b1[f];
    float s = 0.f, ss = 0.f;
    for (int n = blockIdx.x; n < NNODES; n += gridDim.x) {
        const float di = g_dinv[n];
        float v = g_t[(size_t)n * FHID + f] + g_h1[(size_t)n * FHID + f] * di * di + bf;
        v = fmaxf(v, 0.f);
        g_t[(size_t)n * FHID + f] = v;
        s += v; ss += v * v;
    }
    atomicAdd(&g_stats[f], s);
    atomicAdd(&g_stats[FHID + f], ss);
}

// fold BN into per-feature scale/shift
__global__ void k_bnfold(const float* __restrict__ gamma, const float* __restrict__ beta) {
    const int f = threadIdx.x;
    const float inv_n = 1.0f / (float)NNODES;
    const float mean = g_stats[f] * inv_n;
    const float var  = g_stats[FHID + f] * inv_n - mean * mean;
    const float rstd = rsqrtf(var + BN_EPS);
    const float scale = gamma[f] * rstd;
    g_stats[f]        = scale;
    g_stats[FHID + f] = beta[f] - mean * scale;
}

// h2 = bn(t) @ W2.  thread f keeps W2[:,f] (128 vals) in regs; BN applied on row load.
__global__ void __launch_bounds__(FHID, 3) k_gemm2(const float* __restrict__ W2) {
    __shared__ float su[2][FHID];
    const int f = threadIdx.x;
    float w[FHID];
#pragma unroll
    for (int k = 0; k < FHID; k++) w[k] = W2[k * FHID + f];
    const float scale = g_stats[f];
    const float shift = g_stats[FHID + f];

    for (int base = blockIdx.x * 2; base < NNODES; base += gridDim.x * 2) {
        su[0][f] = fmaf(g_t[(size_t)base * FHID + f], scale, shift);
        su[1][f] = fmaf(g_t[(size_t)(base + 1) * FHID + f], scale, shift);
        __syncthreads();
#pragma unroll
        for (int j = 0; j < 2; j++) {
            float acc = 0.f;
#pragma unroll
            for (int k = 0; k < FHID; k++) acc = fmaf(su[j][k], w[k], acc);
            g_h2[(size_t)(base + j) * FHID + f] = acc;
        }
        __syncthreads();
    }
}

// out = relu(agg2 + h2*dinv^2 + b2), agg2 already accumulated in d_out
__global__ void k_finalize2(float* __restrict__ out, const float* __restrict__ b2) {
    const int f = threadIdx.x;
    const float bf = b2[f];
    for (int n = blockIdx.x; n < NNODES; n += gridDim.x) {
        const float di = g_dinv[n];
        float v = out[(size_t)n * FHID + f] + g_h2[(size_t)n * FHID + f] * di * di + bf;
        out[(size_t)n * FHID + f] = fmaxf(v, 0.f);
    }
}

// ---------------- launch ----------------
extern "C" void kernel_launch(void* const* d_in, const int* in_sizes, int n_in,
                              void* d_out, int out_size) {
    const float* x     = (const float*)d_in[0];
    const void*  ei    = d_in[1];                 // [2, E], int32 OR int64 (detected)
    const float* W1    = (const float*)d_in[2];
    const float* b1    = (const float*)d_in[3];
    const float* gamma = (const float*)d_in[4];
    const float* beta  = (const float*)d_in[5];
    const float* W2    = (const float*)d_in[6];
    const float* b2    = (const float*)d_in[7];
    float* out = (float*)d_out;

    k_zero<<<2048, 256>>>((float4*)out);
    k_detect<<<1, 256>>>((const int*)ei);
    k_decode<<<2048, 256>>>(ei);
    k_dinv<<<512, 256>>>();

    k_gemm1<<<888, FHID>>>(x, W1);
    k_scatter1<<<2048, 256>>>();
    k_finalize1<<<1024, FHID>>>(b1);
    k_bnfold<<<1, FHID>>>(gamma, beta);

    k_gemm2<<<444, FHID>>>(W2);
    k_scatter2<<<2048, 256>>>(out);
    k_finalize2<<<1024, FHID>>>(out, b2);
}

// round 5
// speedup vs baseline: 1.8258x; 1.8258x over previous
#include <cuda_runtime.h>
#include <cuda_bf16.h>
#include <stdint.h>

// GCN_57501022159512: 2-layer GCN, N=100000 nodes, E=1600000 edges, 64 -> 128 -> 128.
// h1 = relu(gcnconv(x, W1, b1)); t = batchnorm(h1); out = relu(gcnconv(t, W2, b2))
//
// R5: restore float4 vector atomics in scatter (R1-R3 traps were garbage int64
// indices, not the vector RED instruction). 4x fewer L2 atomic transactions.

#define NNODES 100000
#define NEDGES 1600000
#define FIN    64
#define FHID   128
#define BN_EPS 1e-5f

// ---------------- scratch (device globals; no allocs allowed) ----------------
__device__ float g_h1[NNODES * FHID];    // x @ W1
__device__ float g_t [NNODES * FHID];    // agg1 buffer, then relu/bn input in place
__device__ float g_h2[NNODES * FHID];    // bn(t) @ W2
__device__ float g_dinv[NNODES];
__device__ int   g_deg [NNODES];
__device__ float g_stats[2 * FHID];      // sum,sumsq -> then scale,shift
__device__ int   g_eidx[2 * NEDGES];     // decoded int32 edge index [row | col]
__device__ int   g_is64;

// ---------------- kernels ----------------

__global__ void k_zero(float4* __restrict__ out4) {
    const int idx = blockIdx.x * blockDim.x + threadIdx.x;
    const int stride = gridDim.x * blockDim.x;
    const float4 z = make_float4(0.f, 0.f, 0.f, 0.f);
    float4* t4 = reinterpret_cast<float4*>(g_t);
    const int n4 = NNODES * FHID / 4;
    for (int j = idx; j < n4; j += stride) { t4[j] = z; out4[j] = z; }
    for (int j = idx; j < NNODES; j += stride) g_deg[j] = 0;
    if (idx < 2 * FHID) g_stats[idx] = 0.f;
}

// Detect whether the edge_index buffer is int64 or int32.
__global__ void k_detect(const int* __restrict__ w) {
    __shared__ int bad;
    if (threadIdx.x == 0) bad = 0;
    __syncthreads();
    for (int j = threadIdx.x; j < 1024; j += blockDim.x) {
        const int lo = w[2 * j], hi = w[2 * j + 1];
        if (hi != 0 || lo < 0 || lo >= NNODES) bad = 1;
    }
    __syncthreads();
    if (threadIdx.x == 0) g_is64 = (bad == 0) ? 1 : 0;
}

// Decode edge indices into int32 scratch (clamped defensively) + degree count.
__global__ void k_decode(const void* __restrict__ ei) {
    const int idx = blockIdx.x * blockDim.x + threadIdx.x;
    const int stride = gridDim.x * blockDim.x;
    const bool is64 = (g_is64 != 0);
    const long long* e64 = (const long long*)ei;
    const int*       e32 = (const int*)ei;
    for (int e = idx; e < 2 * NEDGES; e += stride) {
        int v = is64 ? (int)e64[e] : e32[e];
        v = min(max(v, 0), NNODES - 1);
        g_eidx[e] = v;
        if (e >= NEDGES) atomicAdd(&g_deg[v], 1);   // col half -> degree
    }
}

__global__ void k_dinv() {
    const int idx = blockIdx.x * blockDim.x + threadIdx.x;
    const int stride = gridDim.x * blockDim.x;
    for (int n = idx; n < NNODES; n += stride)
        g_dinv[n] = rsqrtf((float)(g_deg[n] + 1));
}

// h1 = x @ W1.  128 threads/block; thread f keeps W1[:,f] (64 vals) in regs.
__global__ void k_gemm1(const float* __restrict__ x, const float* __restrict__ W1) {
    __shared__ float sx[4][FIN];
    const int f = threadIdx.x;
    float w[FIN];
#pragma unroll
    for (int k = 0; k < FIN; k++) w[k] = W1[k * FHID + f];

    for (int base = blockIdx.x * 4; base < NNODES; base += gridDim.x * 4) {
        for (int i = threadIdx.x; i < 4 * FIN; i += FHID)
            sx[i >> 6][i & 63] = x[(size_t)base * FIN + i];
        __syncthreads();
#pragma unroll
        for (int j = 0; j < 4; j++) {
            float acc = 0.f;
#pragma unroll
            for (int k = 0; k < FIN; k++) acc = fmaf(sx[j][k], w[k], acc);
            g_h1[(size_t)(base + j) * FHID + f] = acc;
        }
        __syncthreads();
    }
}

// warp-per-edge scatter: agg[col] += h[row] * dinv[row]*dinv[col]
// 128-bit loads + 128-bit vector reductions (RED.E.ADD.v4.F32).
__device__ __forceinline__ void scatter_body(const float* __restrict__ h,
                                             float* __restrict__ agg) {
    const int lane = threadIdx.x & 31;
    const int warp = (blockIdx.x * blockDim.x + threadIdx.x) >> 5;
    const int nwarps = (gridDim.x * blockDim.x) >> 5;
    for (int e = warp; e < NEDGES; e += nwarps) {
        const int r = g_eidx[e];
        const int c = g_eidx[NEDGES + e];
        const float norm = g_dinv[r] * g_dinv[c];
        float4 v = *reinterpret_cast<const float4*>(h + (size_t)r * FHID + lane * 4);
        v.x *= norm; v.y *= norm; v.z *= norm; v.w *= norm;
        atomicAdd(reinterpret_cast<float4*>(agg + (size_t)c * FHID + lane * 4), v);
    }
}

__global__ void k_scatter1() { scatter_body(g_h1, g_t); }

__global__ void k_scatter2(float* __restrict__ out) { scatter_body(g_h2, out); }

// t = relu(agg1 + h1*dinv^2 + b1), in place in g_t; accumulate BN partial sums.
// 32 threads/feature-quad: thread q handles features [4q, 4q+4) via float4.
__global__ void k_finalize1(const float* __restrict__ b1) {
    const int q = threadIdx.x;               // 0..31 (feature quad)
    const float4 bf = reinterpret_cast<const float4*>(b1)[q];
    float4 s  = make_float4(0.f, 0.f, 0.f, 0.f);
    float4 ss = make_float4(0.f, 0.f, 0.f, 0.f);
    float4* t4  = reinterpret_cast<float4*>(g_t);
    const float4* h4 = reinterpret_cast<const float4*>(g_h1);
    for (int n = blockIdx.x; n < NNODES; n += gridDim.x) {
        const float di = g_dinv[n];
        const float d2 = di * di;
        const size_t o = (size_t)n * (FHID / 4) + q;
        float4 a = t4[o];
        const float4 h = h4[o];
        a.x = fmaxf(fmaf(h.x, d2, a.x) + bf.x, 0.f);
        a.y = fmaxf(fmaf(h.y, d2, a.y) + bf.y, 0.f);
        a.z = fmaxf(fmaf(h.z, d2, a.z) + bf.z, 0.f);
        a.w = fmaxf(fmaf(h.w, d2, a.w) + bf.w, 0.f);
        t4[o] = a;
        s.x += a.x; s.y += a.y; s.z += a.z; s.w += a.w;
        ss.x += a.x * a.x; ss.y += a.y * a.y; ss.z += a.z * a.z; ss.w += a.w * a.w;
    }
    float* st = &g_stats[4 * q];
    atomicAdd(st + 0, s.x); atomicAdd(st + 1, s.y);
    atomicAdd(st + 2, s.z); atomicAdd(st + 3, s.w);
    st = &g_stats[FHID + 4 * q];
    atomicAdd(st + 0, ss.x); atomicAdd(st + 1, ss.y);
    atomicAdd(st + 2, ss.z); atomicAdd(st + 3, ss.w);
}

// fold BN into per-feature scale/shift
__global__ void k_bnfold(const float* __restrict__ gamma, const float* __restrict__ beta) {
    const int f = threadIdx.x;
    const float inv_n = 1.0f / (float)NNODES;
    const float mean = g_stats[f] * inv_n;
    const float var  = g_stats[FHID + f] * inv_n - mean * mean;
    const float rstd = rsqrtf(var + BN_EPS);
    const float scale = gamma[f] * rstd;
    g_stats[f]        = scale;
    g_stats[FHID + f] = beta[f] - mean * scale;
}

// h2 = bn(t) @ W2.  thread f keeps W2[:,f] (128 vals) in regs; BN applied on row load.
__global__ void __launch_bounds__(FHID, 3) k_gemm2(const float* __restrict__ W2) {
    __shared__ float su[2][FHID];
    const int f = threadIdx.x;
    float w[FHID];
#pragma unroll
    for (int k = 0; k < FHID; k++) w[k] = W2[k * FHID + f];
    const float scale = g_stats[f];
    const float shift = g_stats[FHID + f];

    for (int base = blockIdx.x * 2; base < NNODES; base += gridDim.x * 2) {
        su[0][f] = fmaf(g_t[(size_t)base * FHID + f], scale, shift);
        su[1][f] = fmaf(g_t[(size_t)(base + 1) * FHID + f], scale, shift);
        __syncthreads();
#pragma unroll
        for (int j = 0; j < 2; j++) {
            float acc = 0.f;
#pragma unroll
            for (int k = 0; k < FHID; k++) acc = fmaf(su[j][k], w[k], acc);
            g_h2[(size_t)(base + j) * FHID + f] = acc;
        }
        __syncthreads();
    }
}

// out = relu(agg2 + h2*dinv^2 + b2), agg2 already accumulated in d_out
__global__ void k_finalize2(float* __restrict__ out, const float* __restrict__ b2) {
    const int q = threadIdx.x;               // 0..31
    const float4 bf = reinterpret_cast<const float4*>(b2)[q];
    float4* o4 = reinterpret_cast<float4*>(out);
    const float4* h4 = reinterpret_cast<const float4*>(g_h2);
    for (int n = blockIdx.x; n < NNODES; n += gridDim.x) {
        const float di = g_dinv[n];
        const float d2 = di * di;
        const size_t o = (size_t)n * (FHID / 4) + q;
        float4 a = o4[o];
        const float4 h = h4[o];
        a.x = fmaxf(fmaf(h.x, d2, a.x) + bf.x, 0.f);
        a.y = fmaxf(fmaf(h.y, d2, a.y) + bf.y, 0.f);
        a.z = fmaxf(fmaf(h.z, d2, a.z) + bf.z, 0.f);
        a.w = fmaxf(fmaf(h.w, d2, a.w) + bf.w, 0.f);
        o4[o] = a;
    }
}

// ---------------- launch ----------------
extern "C" void kernel_launch(void* const* d_in, const int* in_sizes, int n_in,
                              void* d_out, int out_size) {
    const float* x     = (const float*)d_in[0];
    const void*  ei    = d_in[1];                 // [2, E], int32 OR int64 (detected)
    const float* W1    = (const float*)d_in[2];
    const float* b1    = (const float*)d_in[3];
    const float* gamma = (const float*)d_in[4];
    const float* beta  = (const float*)d_in[5];
    const float* W2    = (const float*)d_in[6];
    const float* b2    = (const float*)d_in[7];
    float* out = (float*)d_out;

    k_zero<<<2048, 256>>>((float4*)out);
    k_detect<<<1, 256>>>((const int*)ei);
    k_decode<<<2048, 256>>>(ei);
    k_dinv<<<512, 256>>>();

    k_gemm1<<<888, FHID>>>(x, W1);
    k_scatter1<<<2048, 256>>>();
    k_finalize1<<<2048, 32>>>(b1);
    k_bnfold<<<1, FHID>>>(gamma, beta);

    k_gemm2<<<444, FHID>>>(W2);
    k_scatter2<<<2048, 256>>>(out);
    k_finalize2<<<2048, 32>>>(out, b2);
}